// round 1
// baseline (speedup 1.0000x reference)
#include <cuda_runtime.h>
#include <math.h>

// QuanvolutionHybrid: algebraically reduced.
// Only feats[:,0] (patch 0, wire 0 <Z>) feeds the rest of the network, so we
// simulate ONE 4-qubit circuit per batch element, then the 1-qubit FC circuit,
// Linear(1,10), log_softmax. One thread per batch element.

__device__ __forceinline__ void rot_mat(float phi, float theta, float omega, float* m) {
    // PennyLane Rot(phi,theta,omega) = RZ(omega) RY(theta) RZ(phi)
    float ct, st;
    sincosf(0.5f * theta, &st, &ct);
    float ca, sa, cb, sb;
    sincosf(0.5f * (phi + omega), &sa, &ca);
    sincosf(0.5f * (phi - omega), &sb, &cb);
    // m00 = e^{-i(phi+omega)/2} ct ; m01 = -e^{+i(phi-omega)/2} st
    // m10 = e^{-i(phi-omega)/2} st ; m11 = e^{+i(phi+omega)/2} ct
    m[0] =  ct * ca;  m[1] = -ct * sa;   // m00 (re, im)
    m[2] = -st * cb;  m[3] = -st * sb;   // m01
    m[4] =  st * cb;  m[5] = -st * sb;   // m10
    m[6] =  ct * ca;  m[7] =  ct * sa;   // m11
}

__global__ void __launch_bounds__(32)
quanv_hybrid_kernel(const float* __restrict__ x,
                    const float* __restrict__ wq,    // [2,2,4,3]
                    const float* __restrict__ wfc,   // [3,3,1,3]
                    const float* __restrict__ Wout,  // [10,1]
                    const float* __restrict__ bout,  // [10]
                    float* __restrict__ out,         // [B,10]
                    int B)
{
    __shared__ float qm[16][8];  // 16 shared Rot gates of the quanv circuit
    __shared__ float fm[9][8];   // 9 shared Rot gates of the fc circuit

    int tid = threadIdx.x;
    if (tid < 16) {
        const float* p = wq + tid * 3;            // gate order = ((app*2+l)*4+w)
        rot_mat(p[0], p[1], p[2], qm[tid]);
    } else if (tid < 25) {
        const float* p = wfc + (tid - 16) * 3;    // gate order = (app*3+l)
        rot_mat(p[0], p[1], p[2], fm[tid - 16]);
    }
    __syncthreads();

    int b = blockIdx.x * 32 + tid;
    if (b >= B) return;

    // Patch 0 of image b: img[0,0], img[0,1], img[1,0], img[1,1]
    const float* xb = x + (size_t)b * 784;
    float thv[4] = { xb[0], xb[1], xb[28], xb[29] };

    // 4-qubit state; wire w = bit (8 >> w) of the flat index (wire 0 = MSB)
    float sr[16], si[16];
#pragma unroll
    for (int i = 0; i < 16; i++) { sr[i] = 0.f; si[i] = 0.f; }
    sr[0] = 1.f;

    // AngleEmbedding: RX(theta_w) on each wire. RX = [[c, -is],[-is, c]]
#pragma unroll
    for (int w = 0; w < 4; w++) {
        float c, s;
        sincosf(0.5f * thv[w], &s, &c);
        const int stride = 8 >> w;
#pragma unroll
        for (int i = 0; i < 16; i++) {
            if (i & stride) continue;
            int j = i | stride;
            float a0r = sr[i], a0i = si[i], a1r = sr[j], a1i = si[j];
            sr[i] =  c * a0r + s * a1i;
            si[i] =  c * a0i - s * a1r;
            sr[j] =  c * a1r + s * a0i;
            si[j] =  c * a1i - s * a0r;
        }
    }

    // StronglyEntanglingLayers: 2 apps x 2 layers of (4 Rot, then CNOT ring)
#pragma unroll
    for (int app = 0; app < 2; app++) {
#pragma unroll
        for (int l = 0; l < 2; l++) {
#pragma unroll
            for (int w = 0; w < 4; w++) {
                const float* m = qm[(app * 2 + l) * 4 + w];
                float m00r = m[0], m00i = m[1], m01r = m[2], m01i = m[3];
                float m10r = m[4], m10i = m[5], m11r = m[6], m11i = m[7];
                const int stride = 8 >> w;
#pragma unroll
                for (int i = 0; i < 16; i++) {
                    if (i & stride) continue;
                    int j = i | stride;
                    float a0r = sr[i], a0i = si[i], a1r = sr[j], a1i = si[j];
                    sr[i] = m00r * a0r - m00i * a0i + m01r * a1r - m01i * a1i;
                    si[i] = m00r * a0i + m00i * a0r + m01r * a1i + m01i * a1r;
                    sr[j] = m10r * a0r - m10i * a0i + m11r * a1r - m11i * a1i;
                    si[j] = m10r * a0i + m10i * a0r + m11r * a1i + m11i * a1r;
                }
            }
            const int r = (l == 0) ? 1 : 2;   // SEL ranges
#pragma unroll
            for (int w = 0; w < 4; w++) {
                int t = (w + r) & 3;
                const int sc = 8 >> w, stt = 8 >> t;
#pragma unroll
                for (int i = 0; i < 16; i++) {
                    if ((i & sc) && !(i & stt)) {
                        int j = i | stt;
                        float tr = sr[i], ti = si[i];
                        sr[i] = sr[j]; si[i] = si[j];
                        sr[j] = tr;    si[j] = ti;
                    }
                }
            }
        }
    }

    // <Z_0> = P(bit0=0) - P(bit0=1); bit0 = i>>3
    float ez = 0.f;
#pragma unroll
    for (int i = 0; i < 16; i++) {
        float p = sr[i] * sr[i] + si[i] * si[i];
        ez += (i < 8) ? p : -p;
    }

    // 1-qubit FC circuit: RX(ez)|0> then 9 shared Rot gates
    float c0, s0;
    sincosf(0.5f * ez, &s0, &c0);
    float a0r = c0, a0i = 0.f, a1r = 0.f, a1i = -s0;
#pragma unroll
    for (int g = 0; g < 9; g++) {
        const float* m = fm[g];
        float n0r = m[0] * a0r - m[1] * a0i + m[2] * a1r - m[3] * a1i;
        float n0i = m[0] * a0i + m[1] * a0r + m[2] * a1i + m[3] * a1r;
        float n1r = m[4] * a0r - m[5] * a0i + m[6] * a1r - m[7] * a1i;
        float n1i = m[4] * a0i + m[5] * a0r + m[6] * a1i + m[7] * a1r;
        a0r = n0r; a0i = n0i; a1r = n1r; a1i = n1i;
    }
    float q = (a0r * a0r + a0i * a0i) - (a1r * a1r + a1i * a1i);

    // Linear(1,10) + log_softmax
    float lg[10], mx = -1e30f;
#pragma unroll
    for (int k = 0; k < 10; k++) {
        lg[k] = q * Wout[k] + bout[k];
        mx = fmaxf(mx, lg[k]);
    }
    float se = 0.f;
#pragma unroll
    for (int k = 0; k < 10; k++) se += expf(lg[k] - mx);
    float lse = logf(se);
    float* ob = out + (size_t)b * 10;
#pragma unroll
    for (int k = 0; k < 10; k++) ob[k] = lg[k] - mx - lse;
}

extern "C" void kernel_launch(void* const* d_in, const int* in_sizes, int n_in,
                              void* d_out, int out_size) {
    const float* x    = (const float*)d_in[0];   // [B,784]
    const float* wq   = (const float*)d_in[1];   // [2,2,4,3] = 48
    const float* wfc  = (const float*)d_in[2];   // [3,3,1,3] = 27
    const float* Wout = (const float*)d_in[3];   // [10,1]
    const float* bout = (const float*)d_in[4];   // [10]
    float* out = (float*)d_out;                  // [B,10]

    int B = in_sizes[0] / 784;
    int blocks = (B + 31) / 32;
    quanv_hybrid_kernel<<<blocks, 32>>>(x, wq, wfc, Wout, bout, out, B);
}

// round 2
// speedup vs baseline: 1.0029x; 1.0029x over previous
#include <cuda_runtime.h>
#include <math.h>

// QuanvolutionHybrid, algebraically reduced:
// only feats[:,0] (patch 0, wire 0 <Z>) feeds the FC stage, so we simulate ONE
// 4-qubit circuit per batch element + 1-qubit FC circuit + Linear(1,10) + log_softmax.
// One thread per batch element; issue-bound on one warp/SM, so minimize instructions:
// fast MUFU intrinsics, float4 SMEM matrix loads, float2 stores, SMEM-staged Wout/bout.

__device__ __forceinline__ void rot_mat_fast(float phi, float theta, float omega, float4* m) {
    // PennyLane Rot(phi,theta,omega) = RZ(omega) RY(theta) RZ(phi)
    float ct, st, ca, sa, cb, sb;
    __sincosf(0.5f * theta, &st, &ct);
    __sincosf(0.5f * (phi + omega), &sa, &ca);
    __sincosf(0.5f * (phi - omega), &sb, &cb);
    // rows: (m00r,m00i,m01r,m01i) , (m10r,m10i,m11r,m11i)
    m[0] = make_float4( ct * ca, -ct * sa, -st * cb, -st * sb);
    m[1] = make_float4( st * cb, -st * sb,  ct * ca,  ct * sa);
}

__global__ void __launch_bounds__(32)
quanv_hybrid_kernel(const float* __restrict__ x,
                    const float* __restrict__ wq,    // [2,2,4,3]
                    const float* __restrict__ wfc,   // [3,3,1,3]
                    const float* __restrict__ Wout,  // [10,1]
                    const float* __restrict__ bout,  // [10]
                    float* __restrict__ out,         // [B,10]
                    int B)
{
    __shared__ float4 qm[16][2];   // 16 shared Rot gates (quanv)
    __shared__ float4 fm[9][2];    // 9 shared Rot gates (fc)
    __shared__ float  wo[10], bo[10];

    const int tid = threadIdx.x;
    const int b = blockIdx.x * 32 + tid;

    // Issue the global loads FIRST so DRAM latency overlaps the prologue math.
    float2 p01 = make_float2(0.f, 0.f), p23 = make_float2(0.f, 0.f);
    if (b < B) {
        const float* xb = x + (size_t)b * 784;
        p01 = *(const float2*)(xb);        // img[0,0], img[0,1]
        p23 = *(const float2*)(xb + 28);   // img[1,0], img[1,1]
    }

    // Prologue: build shared gate matrices + stage Wout/bout.
    if (tid < 16) {
        const float* p = wq + tid * 3;            // gate order ((app*2+l)*4+w)
        rot_mat_fast(p[0], p[1], p[2], qm[tid]);
    } else if (tid < 25) {
        const float* p = wfc + (tid - 16) * 3;    // gate order (app*3+l)
        rot_mat_fast(p[0], p[1], p[2], fm[tid - 16]);
    } else if (tid == 25) {
#pragma unroll
        for (int k = 0; k < 10; k++) wo[k] = __ldg(Wout + k);
    } else if (tid == 26) {
#pragma unroll
        for (int k = 0; k < 10; k++) bo[k] = __ldg(bout + k);
    }
    __syncthreads();

    if (b >= B) return;

    // 4-qubit state; wire w = bit (8 >> w) of the flat index (wire 0 = MSB)
    float sr[16], si[16];
#pragma unroll
    for (int i = 0; i < 16; i++) { sr[i] = 0.f; si[i] = 0.f; }
    sr[0] = 1.f;

    // AngleEmbedding: RX(theta_w) per wire. RX = [[c, -is],[-is, c]]
    const float thv[4] = { p01.x, p01.y, p23.x, p23.y };
#pragma unroll
    for (int w = 0; w < 4; w++) {
        float c, s;
        __sincosf(0.5f * thv[w], &s, &c);
        const int stride = 8 >> w;
#pragma unroll
        for (int i = 0; i < 16; i++) {
            if (i & stride) continue;
            int j = i | stride;
            float a0r = sr[i], a0i = si[i], a1r = sr[j], a1i = si[j];
            sr[i] =  c * a0r + s * a1i;
            si[i] =  c * a0i - s * a1r;
            sr[j] =  c * a1r + s * a0i;
            si[j] =  c * a1i - s * a0r;
        }
    }

    // StronglyEntanglingLayers: 2 apps x 2 layers of (4 Rot, then CNOT ring)
#pragma unroll
    for (int app = 0; app < 2; app++) {
#pragma unroll
        for (int l = 0; l < 2; l++) {
#pragma unroll
            for (int w = 0; w < 4; w++) {
                const float4 mA = qm[(app * 2 + l) * 4 + w][0];
                const float4 mB = qm[(app * 2 + l) * 4 + w][1];
                const int stride = 8 >> w;
#pragma unroll
                for (int i = 0; i < 16; i++) {
                    if (i & stride) continue;
                    int j = i | stride;
                    float a0r = sr[i], a0i = si[i], a1r = sr[j], a1i = si[j];
                    sr[i] = mA.x * a0r - mA.y * a0i + mA.z * a1r - mA.w * a1i;
                    si[i] = mA.x * a0i + mA.y * a0r + mA.z * a1i + mA.w * a1r;
                    sr[j] = mB.x * a0r - mB.y * a0i + mB.z * a1r - mB.w * a1i;
                    si[j] = mB.x * a0i + mB.y * a0r + mB.z * a1i + mB.w * a1r;
                }
            }
            const int r = (l == 0) ? 1 : 2;   // SEL ranges
#pragma unroll
            for (int w = 0; w < 4; w++) {
                int t = (w + r) & 3;
                const int sc = 8 >> w, stt = 8 >> t;
#pragma unroll
                for (int i = 0; i < 16; i++) {
                    if ((i & sc) && !(i & stt)) {
                        int j = i | stt;
                        float tr = sr[i], ti = si[i];
                        sr[i] = sr[j]; si[i] = si[j];
                        sr[j] = tr;    si[j] = ti;
                    }
                }
            }
        }
    }

    // <Z_0> = P(bit0=0) - P(bit0=1); bit0 = i>>3
    float ez = 0.f;
#pragma unroll
    for (int i = 0; i < 16; i++) {
        float p = fmaf(sr[i], sr[i], si[i] * si[i]);
        ez += (i < 8) ? p : -p;
    }

    // 1-qubit FC circuit: RX(ez)|0> then 9 shared Rot gates
    float c0, s0;
    __sincosf(0.5f * ez, &s0, &c0);
    float a0r = c0, a0i = 0.f, a1r = 0.f, a1i = -s0;
#pragma unroll
    for (int g = 0; g < 9; g++) {
        const float4 mA = fm[g][0];
        const float4 mB = fm[g][1];
        float n0r = mA.x * a0r - mA.y * a0i + mA.z * a1r - mA.w * a1i;
        float n0i = mA.x * a0i + mA.y * a0r + mA.z * a1i + mA.w * a1r;
        float n1r = mB.x * a0r - mB.y * a0i + mB.z * a1r - mB.w * a1i;
        float n1i = mB.x * a0i + mB.y * a0r + mB.z * a1i + mB.w * a1r;
        a0r = n0r; a0i = n0i; a1r = n1r; a1i = n1i;
    }
    float q = (a0r * a0r + a0i * a0i) - (a1r * a1r + a1i * a1i);

    // Linear(1,10) + log_softmax
    float lg[10], mx = -1e30f;
#pragma unroll
    for (int k = 0; k < 10; k++) {
        lg[k] = fmaf(q, wo[k], bo[k]);
        mx = fmaxf(mx, lg[k]);
    }
    float se = 0.f;
#pragma unroll
    for (int k = 0; k < 10; k++) se += __expf(lg[k] - mx);
    const float off = mx + __logf(se);

    float2* ob = (float2*)(out + (size_t)b * 10);  // 40B row stride -> 8B aligned
#pragma unroll
    for (int k = 0; k < 5; k++)
        ob[k] = make_float2(lg[2 * k] - off, lg[2 * k + 1] - off);
}

extern "C" void kernel_launch(void* const* d_in, const int* in_sizes, int n_in,
                              void* d_out, int out_size) {
    const float* x    = (const float*)d_in[0];   // [B,784]
    const float* wq   = (const float*)d_in[1];   // [2,2,4,3]
    const float* wfc  = (const float*)d_in[2];   // [3,3,1,3]
    const float* Wout = (const float*)d_in[3];   // [10,1]
    const float* bout = (const float*)d_in[4];   // [10]
    float* out = (float*)d_out;                  // [B,10]

    int B = in_sizes[0] / 784;
    int blocks = (B + 31) / 32;
    quanv_hybrid_kernel<<<blocks, 32>>>(x, wq, wfc, Wout, bout, out, B);
}

// round 3
// speedup vs baseline: 1.6618x; 1.6570x over previous
#include <cuda_runtime.h>
#include <math.h>

// QuanvolutionHybrid, algebraically reduced + 4-way state-split.
// Only feats[:,0] (patch 0, wire 0 <Z>) feeds the FC stage. Each sample's
// 16-amplitude 4-qubit state is split across 4 threads (4 amps each):
//   amp index i = g*4 + loc ; thread sub-lane g = (wire0,wire1), loc = (wire2,wire3)
// Wires 2,3 gates are thread-local; wires 0,1 gates use shfl_xor exchanges.
// 16384 threads = 512 warps (~3.5/SM) so latencies overlap across warps.

#define SHX(v, m) __shfl_xor_sync(0xffffffffu, (v), (m))
#define SH4(v, l) __shfl_sync(0xffffffffu, (v), (l), 4)

__device__ __forceinline__ void rot_mat_fast(float phi, float theta, float omega, float4* m) {
    // PennyLane Rot(phi,theta,omega) = RZ(omega) RY(theta) RZ(phi)
    float ct, st, ca, sa, cb, sb;
    __sincosf(0.5f * theta, &st, &ct);
    __sincosf(0.5f * (phi + omega), &sa, &ca);
    __sincosf(0.5f * (phi - omega), &sb, &cb);
    m[0] = make_float4( ct * ca, -ct * sa, -st * cb, -st * sb);  // m00, m01
    m[1] = make_float4( st * cb, -st * sb,  ct * ca,  ct * sa);  // m10, m11
}

// Local gate on a pair of this thread's amps (P = bit0 side, Q = bit1 side)
#define ROT_LOCAL_PAIR(P, Q, mA, mB) {                                        \
    float n0r = mA.x*ar##P - mA.y*ai##P + mA.z*ar##Q - mA.w*ai##Q;            \
    float n0i = mA.x*ai##P + mA.y*ar##P + mA.z*ai##Q + mA.w*ar##Q;            \
    float n1r = mB.x*ar##P - mB.y*ai##P + mB.z*ar##Q - mB.w*ai##Q;            \
    float n1i = mB.x*ai##P + mB.y*ar##P + mB.z*ai##Q + mB.w*ar##Q;            \
    ar##P = n0r; ai##P = n0i; ar##Q = n1r; ai##Q = n1i; }

#define ROT_CROSS_AMP(K, mask) {                                              \
    float pr = SHX(ar##K, mask), pi = SHX(ai##K, mask);                       \
    float nr = csr*ar##K - csi*ai##K + cpr*pr - cpi*pi;                       \
    float ni = csr*ai##K + csi*ar##K + cpr*pi + cpi*pr;                       \
    ar##K = nr; ai##K = ni; }

// Cross-thread gate on wire held in sub-lane bits; BIT = this thread's wire bit
#define ROT_CROSS(mask, BIT, mA, mB) {                                        \
    float csr = (BIT) ? mB.z : mA.x, csi = (BIT) ? mB.w : mA.y;               \
    float cpr = (BIT) ? mB.x : mA.z, cpi = (BIT) ? mB.y : mA.w;               \
    ROT_CROSS_AMP(0, mask) ROT_CROSS_AMP(1, mask)                             \
    ROT_CROSS_AMP(2, mask) ROT_CROSS_AMP(3, mask) }

// RX cross gate: m00=m11=(c,0), m01=m10=(0,-s) -> no bit-dependent selects
#define RX_CROSS_AMP(K, mask) {                                               \
    float pr = SHX(ar##K, mask), pi = SHX(ai##K, mask);                       \
    float nr = cw*ar##K + sw*pi;                                              \
    float ni = cw*ai##K - sw*pr;                                              \
    ar##K = nr; ai##K = ni; }

#define RX_LOCAL_PAIR(P, Q) {                                                 \
    float n0r = cw*ar##P + sw*ai##Q, n0i = cw*ai##P - sw*ar##Q;               \
    float n1r = cw*ar##Q + sw*ai##P, n1i = cw*ai##Q - sw*ar##P;               \
    ar##P = n0r; ai##P = n0i; ar##Q = n1r; ai##Q = n1i; }

// Predicated local swap of two complex amps (SEL, no branch)
#define CSWAP1(P, A, Bv) { float t_ = (P) ? Bv : A; float u_ = (P) ? A : Bv; A = t_; Bv = u_; }
#define CSWAP_PAIR(P, I, J) CSWAP1(P, ar##I, ar##J) CSWAP1(P, ai##I, ai##J)

// Unconditional cross exchange of one complex amp with partner
#define XCHG(K, mask) { ar##K = SHX(ar##K, mask); ai##K = SHX(ai##K, mask); }

__global__ void __launch_bounds__(128)
quanv_hybrid_kernel(const float* __restrict__ x,
                    const float* __restrict__ wq,    // [2,2,4,3]
                    const float* __restrict__ wfc,   // [3,3,1,3]
                    const float* __restrict__ Wout,  // [10,1]
                    const float* __restrict__ bout,  // [10]
                    float* __restrict__ out,         // [B,10]
                    int B)
{
    __shared__ float4 qm[16][2];
    __shared__ float4 fm[9][2];
    __shared__ float  wo[10], bo[10];

    const int tid = threadIdx.x;
    const int g   = tid & 3;                 // sub-lane within sample group
    const int s   = blockIdx.x * 32 + (tid >> 2);
    const int scl = (s < B) ? s : (B - 1);

    // own pixel: wire g's angle; patch 0 offsets {0,1,28,29}
    const int off = (g & 1) + (g >> 1) * 28;
    const float pix = x[(size_t)scl * 784 + off];

    // Prologue: shared gate matrices + Wout/bout staging
    if (tid < 16) {
        const float* p = wq + tid * 3;            // gate ((app*2+l)*4+w)
        rot_mat_fast(p[0], p[1], p[2], qm[tid]);
    } else if (tid < 25) {
        const float* p = wfc + (tid - 16) * 3;    // gate (app*3+l)
        rot_mat_fast(p[0], p[1], p[2], fm[tid - 16]);
    } else if (tid == 25) {
#pragma unroll
        for (int k = 0; k < 10; k++) wo[k] = __ldg(Wout + k);
    } else if (tid == 26) {
#pragma unroll
        for (int k = 0; k < 10; k++) bo[k] = __ldg(bout + k);
    }

    float co, so;
    __sincosf(0.5f * pix, &so, &co);

    const bool b1 = (g >> 1) & 1;   // wire0 bit of this thread
    const bool b0 = g & 1;          // wire1 bit of this thread

    // 4 local amps (loc = wire2,wire3 bits); global |0000> -> g==0, loc==0
    float ar0 = (g == 0) ? 1.f : 0.f, ai0 = 0.f;
    float ar1 = 0.f, ai1 = 0.f, ar2 = 0.f, ai2 = 0.f, ar3 = 0.f, ai3 = 0.f;

    __syncthreads();

    // ---- AngleEmbedding: RX per wire ----
    { float cw = SH4(co, 0), sw = SH4(so, 0);   // wire0: cross, mask 2
      RX_CROSS_AMP(0, 2) RX_CROSS_AMP(1, 2) RX_CROSS_AMP(2, 2) RX_CROSS_AMP(3, 2) }
    { float cw = SH4(co, 1), sw = SH4(so, 1);   // wire1: cross, mask 1
      RX_CROSS_AMP(0, 1) RX_CROSS_AMP(1, 1) RX_CROSS_AMP(2, 1) RX_CROSS_AMP(3, 1) }
    { float cw = SH4(co, 2), sw = SH4(so, 2);   // wire2: local pairs (0,2),(1,3)
      RX_LOCAL_PAIR(0, 2) RX_LOCAL_PAIR(1, 3) }
    { float cw = SH4(co, 3), sw = SH4(so, 3);   // wire3: local pairs (0,1),(2,3)
      RX_LOCAL_PAIR(0, 1) RX_LOCAL_PAIR(2, 3) }

    // ---- StronglyEntanglingLayers: 2 apps x 2 layers ----
#pragma unroll
    for (int app = 0; app < 2; app++) {
        const int gbase = app * 8;
        // ----- layer l=0 (range r=1) -----
        { const float4 mA = qm[gbase + 0][0], mB = qm[gbase + 0][1];
          ROT_CROSS(2, b1, mA, mB) }
        { const float4 mA = qm[gbase + 1][0], mB = qm[gbase + 1][1];
          ROT_CROSS(1, b0, mA, mB) }
        { const float4 mA = qm[gbase + 2][0], mB = qm[gbase + 2][1];
          ROT_LOCAL_PAIR(0, 2, mA, mB) ROT_LOCAL_PAIR(1, 3, mA, mB) }
        { const float4 mA = qm[gbase + 3][0], mB = qm[gbase + 3][1];
          ROT_LOCAL_PAIR(0, 1, mA, mB) ROT_LOCAL_PAIR(2, 3, mA, mB) }
        // CNOT(0,1): if b1, exchange whole state with partner g^1
        { float q0r = SHX(ar0, 1), q0i = SHX(ai0, 1), q1r = SHX(ar1, 1), q1i = SHX(ai1, 1);
          float q2r = SHX(ar2, 1), q2i = SHX(ai2, 1), q3r = SHX(ar3, 1), q3i = SHX(ai3, 1);
          ar0 = b1 ? q0r : ar0; ai0 = b1 ? q0i : ai0;
          ar1 = b1 ? q1r : ar1; ai1 = b1 ? q1i : ai1;
          ar2 = b1 ? q2r : ar2; ai2 = b1 ? q2i : ai2;
          ar3 = b1 ? q3r : ar3; ai3 = b1 ? q3i : ai3; }
        // CNOT(1,2): if b0, swap (0<->2),(1<->3)
        CSWAP_PAIR(b0, 0, 2) CSWAP_PAIR(b0, 1, 3)
        // CNOT(2,3): swap amps 2,3 (control locbit1)
        { float t = ar2; ar2 = ar3; ar3 = t; t = ai2; ai2 = ai3; ai3 = t; }
        // CNOT(3,0): locs {1,3} exchange with partner g^2
        XCHG(1, 2) XCHG(3, 2)

        // ----- layer l=1 (range r=2) -----
        { const float4 mA = qm[gbase + 4][0], mB = qm[gbase + 4][1];
          ROT_CROSS(2, b1, mA, mB) }
        { const float4 mA = qm[gbase + 5][0], mB = qm[gbase + 5][1];
          ROT_CROSS(1, b0, mA, mB) }
        { const float4 mA = qm[gbase + 6][0], mB = qm[gbase + 6][1];
          ROT_LOCAL_PAIR(0, 2, mA, mB) ROT_LOCAL_PAIR(1, 3, mA, mB) }
        { const float4 mA = qm[gbase + 7][0], mB = qm[gbase + 7][1];
          ROT_LOCAL_PAIR(0, 1, mA, mB) ROT_LOCAL_PAIR(2, 3, mA, mB) }
        // CNOT(0,2): if b1 swap (0<->2),(1<->3)
        CSWAP_PAIR(b1, 0, 2) CSWAP_PAIR(b1, 1, 3)
        // CNOT(1,3): if b0 swap (0<->1),(2<->3)
        CSWAP_PAIR(b0, 0, 1) CSWAP_PAIR(b0, 2, 3)
        // CNOT(2,0): locs {2,3} exchange with partner g^2
        XCHG(2, 2) XCHG(3, 2)
        // CNOT(3,1): locs {1,3} exchange with partner g^1
        XCHG(1, 1) XCHG(3, 1)
    }

    // ---- <Z_0> : sign by wire0 bit (b1), reduce across the 4-lane group ----
    float part = ar0*ar0 + ai0*ai0 + ar1*ar1 + ai1*ai1
               + ar2*ar2 + ai2*ai2 + ar3*ar3 + ai3*ai3;
    part = b1 ? -part : part;
    part += SHX(part, 1);
    part += SHX(part, 2);
    const float ez = part;

    // ---- 1-qubit FC circuit: RX(ez)|0>, then 9 shared Rot gates ----
    float c0, s0;
    __sincosf(0.5f * ez, &s0, &c0);
    float a0r = c0, a0i = 0.f, a1r = 0.f, a1i = -s0;
#pragma unroll
    for (int gi = 0; gi < 9; gi++) {
        const float4 mA = fm[gi][0];
        const float4 mB = fm[gi][1];
        float n0r = mA.x*a0r - mA.y*a0i + mA.z*a1r - mA.w*a1i;
        float n0i = mA.x*a0i + mA.y*a0r + mA.z*a1i + mA.w*a1r;
        float n1r = mB.x*a0r - mB.y*a0i + mB.z*a1r - mB.w*a1i;
        float n1i = mB.x*a0i + mB.y*a0r + mB.z*a1i + mB.w*a1r;
        a0r = n0r; a0i = n0i; a1r = n1r; a1i = n1i;
    }
    const float qv = (a0r*a0r + a0i*a0i) - (a1r*a1r + a1i*a1i);

    // ---- Linear(1,10) + log_softmax (computed redundantly per lane) ----
    float mx = -1e30f;
    float lg8 = 0.f, lg9 = 0.f;
#pragma unroll
    for (int k = 0; k < 10; k++) {
        float v = fmaf(qv, wo[k], bo[k]);
        mx = fmaxf(mx, v);
        if (k == 8) lg8 = v;
        if (k == 9) lg9 = v;
    }
    float se = 0.f;
#pragma unroll
    for (int k = 0; k < 10; k++) se += __expf(fmaf(qv, wo[k], bo[k]) - mx);
    const float off2 = mx + __logf(se);

    if (s < B) {
        float2* ob = (float2*)(out + (size_t)s * 10);   // 40B rows -> 8B aligned
        const float e0 = fmaf(qv, wo[2 * g],     bo[2 * g])     - off2;
        const float e1 = fmaf(qv, wo[2 * g + 1], bo[2 * g + 1]) - off2;
        ob[g] = make_float2(e0, e1);                    // pairs 0..3
        if (g == 0) ob[4] = make_float2(lg8 - off2, lg9 - off2);
    }
}

extern "C" void kernel_launch(void* const* d_in, const int* in_sizes, int n_in,
                              void* d_out, int out_size) {
    const float* x    = (const float*)d_in[0];   // [B,784]
    const float* wq   = (const float*)d_in[1];   // [2,2,4,3]
    const float* wfc  = (const float*)d_in[2];   // [3,3,1,3]
    const float* Wout = (const float*)d_in[3];   // [10,1]
    const float* bout = (const float*)d_in[4];   // [10]
    float* out = (float*)d_out;                  // [B,10]

    int B = in_sizes[0] / 784;
    int blocks = (B + 31) / 32;                  // 32 samples per 128-thread block
    quanv_hybrid_kernel<<<blocks, 128>>>(x, wq, wfc, Wout, bout, out, B);
}